// round 15
// baseline (speedup 1.0000x reference)
#include <cuda_runtime.h>
#include <cuda_bf16.h>
#include <cuda_fp16.h>
#include <cstdint>
#include <stdint.h>
#include <math.h>

#define NN 2000
#define BB 8
#define LL 12
#define DD 2
#define HH 64
#define EE 16000
#define ETOT 18000
#define NSEQ (NN*BB)                 // 16000
#define OUT1_ELEMS (NSEQ*LL*HH)      // 12,288,000
#define NPB 14                       // nodes per precompute block
#define PRE_GRID ((NN + NPB - 1) / NPB)

__device__ float  g_out1[OUT1_ELEMS];
__device__ __half g_out1h[OUT1_ELEMS];              // fp16 mirror for edge msg
__device__ float  g_agg[OUT1_ELEMS];
__device__ __half g_Yh[(size_t)NN * 6 * 96 * 64];   // 147.5 MB fp16 planes

// ---------------------------------------------------------------------------
// FMA-only fast math (no MUFU)
// ---------------------------------------------------------------------------
__device__ __forceinline__ float fexp2(float y) {
    y = fminf(fmaxf(y, -125.0f), 125.0f);
    float r = __fadd_rn(y, 12582912.0f);
    int   n = __float_as_int(r) - 0x4B400000;
    float f = __fsub_rn(y, __fsub_rn(r, 12582912.0f));
    float u = f * 0.69314718055994531f;
    float p = fmaf(u, 1.3888889e-3f, 8.3333333e-3f);
    p = fmaf(u, p, 4.1666667e-2f);
    p = fmaf(u, p, 1.6666667e-1f);
    p = fmaf(u, p, 0.5f);
    p = fmaf(u, p, 1.0f);
    p = fmaf(u, p, 1.0f);
    return p * __int_as_float((n + 127) << 23);
}
__device__ __forceinline__ float frcp(float x) {
    float r = __int_as_float(0x7EF311C3 - __float_as_int(x));
    r = r * __fmaf_rn(-x, r, 2.0f);
    r = r * __fmaf_rn(-x, r, 2.0f);
    r = r * __fmaf_rn(-x, r, 2.0f);
    return r;
}
__device__ __forceinline__ float fsig(float x) {
    return frcp(1.0f + fexp2(-1.4426950408889634f * x));
}
__device__ __forceinline__ float ftanh(float x) {
    float e = fexp2(2.8853900817779268f * x);
    return fmaf(-2.0f, frcp(1.0f + e), 1.0f);
}

// ---------------------------------------------------------------------------
// mma.sync / ldmatrix helpers (sm_80+ path, legal on sm_103)
// ---------------------------------------------------------------------------
__device__ __forceinline__ uint32_t smem_u32(const void* p) {
    uint32_t a;
    asm("{ .reg .u64 t; cvta.to.shared.u64 t, %1; cvt.u32.u64 %0, t; }"
        : "=r"(a) : "l"(p));
    return a;
}
__device__ __forceinline__ void ldmx4(uint32_t* r, uint32_t addr) {
    asm volatile("ldmatrix.sync.aligned.m8n8.x4.shared.b16 {%0,%1,%2,%3}, [%4];"
                 : "=r"(r[0]), "=r"(r[1]), "=r"(r[2]), "=r"(r[3]) : "r"(addr));
}
__device__ __forceinline__ void mma16816(float* d, const uint32_t* a, const uint32_t* b) {
    asm volatile("mma.sync.aligned.m16n8k16.row.col.f32.bf16.bf16.f32 "
                 "{%0,%1,%2,%3}, {%4,%5,%6,%7}, {%8,%9}, {%0,%1,%2,%3};"
                 : "+f"(d[0]), "+f"(d[1]), "+f"(d[2]), "+f"(d[3])
                 : "r"(a[0]), "r"(a[1]), "r"(a[2]), "r"(a[3]),
                   "r"(b[0]), "r"(b[1]));
}
// tiles with 64 bf16 per row (128 B = 8 x 16B units), unit ^= (row&7)
__device__ __forceinline__ uint32_t tb64(int row, int k) {
    return (uint32_t)(row * 8 + ((k >> 3) ^ (row & 7))) * 16u
         + (uint32_t)(k & 7) * 2u;
}
__device__ __forceinline__ float4 h4_to_f4(uint2 u) {
    float2 lo = __half22float2(*(__half2*)&u.x);
    float2 hi = __half22float2(*(__half2*)&u.y);
    float4 r; r.x = lo.x; r.y = lo.y; r.z = hi.x; r.w = hi.y;
    return r;
}

// ---------------------------------------------------------------------------
// GRU1: 4 seqs/thread (proven) + fp16 mirror store
// ---------------------------------------------------------------------------
extern "C" __global__ void gru1_kernel(const float* __restrict__ data,
                                       const float* __restrict__ Wih,
                                       const float* __restrict__ Whh,
                                       const float* __restrict__ bih,
                                       const float* __restrict__ bhh,
                                       float* __restrict__ h1_out)
{
    extern __shared__ float sm[];
    float* whhT = sm;
    float* h_sh = sm + 12352;
    float* x_sh = sm + 12352 + 1024;

    const int tid = threadIdx.x;
    const int grp = tid >> 6;
    const int j   = tid & 63;

    for (int idx = tid; idx < 12288; idx += 256) {
        int g = idx >> 6, k = idx & 63;
        int m = g >> 6, jj = g & 63;
        whhT[k * 193 + m * 64 + jj] = Whh[idx];
    }
    for (int idx = tid; idx < 384; idx += 256)
        x_sh[idx] = data[(size_t)blockIdx.x * 384 + idx];

    float wr0 = Wih[j * 2],        wr1 = Wih[j * 2 + 1];
    float wz0 = Wih[(64 + j) * 2], wz1 = Wih[(64 + j) * 2 + 1];
    float wn0 = Wih[(128 + j)* 2], wn1 = Wih[(128 + j)* 2 + 1];
    float br = bih[j], bz = bih[64 + j], bn = bih[128 + j];
    float cr = bhh[j], cz = bhh[64 + j], cn = bhh[128 + j];

    float h[4] = {0.f, 0.f, 0.f, 0.f};
    const int s0 = blockIdx.x * 16 + grp * 4;
    float*  outb = g_out1  + (size_t)s0 * 768 + j;
    __half* outh = g_out1h + (size_t)s0 * 768 + j;

    for (int l = 0; l < LL; l++) {
        *(float4*)&h_sh[grp * 256 + j * 4] = make_float4(h[0], h[1], h[2], h[3]);
        __syncthreads();

        float ghr[4], ghz[4], ghn[4];
        #pragma unroll
        for (int s = 0; s < 4; s++) { ghr[s] = cr; ghz[s] = cz; ghn[s] = cn; }

        const float* wp = whhT + j;
        const float* hp = h_sh + grp * 256;
        #pragma unroll 4
        for (int k = 0; k < 64; k++) {
            float w0 = wp[k * 193];
            float w1 = wp[k * 193 + 64];
            float w2 = wp[k * 193 + 128];
            float4 hv = *(const float4*)&hp[k * 4];
            ghr[0] = fmaf(hv.x, w0, ghr[0]); ghz[0] = fmaf(hv.x, w1, ghz[0]); ghn[0] = fmaf(hv.x, w2, ghn[0]);
            ghr[1] = fmaf(hv.y, w0, ghr[1]); ghz[1] = fmaf(hv.y, w1, ghz[1]); ghn[1] = fmaf(hv.y, w2, ghn[1]);
            ghr[2] = fmaf(hv.z, w0, ghr[2]); ghz[2] = fmaf(hv.z, w1, ghz[2]); ghn[2] = fmaf(hv.z, w2, ghn[2]);
            ghr[3] = fmaf(hv.w, w0, ghr[3]); ghz[3] = fmaf(hv.w, w1, ghz[3]); ghn[3] = fmaf(hv.w, w2, ghn[3]);
        }
        #pragma unroll
        for (int s = 0; s < 4; s++) {
            float x0 = x_sh[(grp * 4 + s) * 24 + l * 2];
            float x1 = x_sh[(grp * 4 + s) * 24 + l * 2 + 1];
            float gir = fmaf(x1, wr1, fmaf(x0, wr0, br));
            float giz = fmaf(x1, wz1, fmaf(x0, wz0, bz));
            float gin = fmaf(x1, wn1, fmaf(x0, wn0, bn));
            float r = fsig(gir + ghr[s]);
            float z = fsig(giz + ghz[s]);
            float n = ftanh(fmaf(r, ghn[s], gin));
            h[s] = fmaf(z, h[s] - n, n);
            outb[s * 768 + l * 64] = h[s];
            outh[s * 768 + l * 64] = __float2half(h[s]);
        }
        __syncthreads();
    }
    #pragma unroll
    for (int s = 0; s < 4; s++)
        h1_out[(s0 + s) * 64 + j] = h[s];
}

// ---------------------------------------------------------------------------
// Precompute kernel (unchanged, proven): per node n, 6 fp16 planes
// ---------------------------------------------------------------------------
#define PC_BH 0
#define PC_BL 49152
#define PC_XH 98304
#define PC_XL 110592
#define PC_SMEM 122880

extern "C" __global__ void __launch_bounds__(256, 1)
precomp_kernel(const float* __restrict__ W3, const float* __restrict__ b3)
{
    extern __shared__ char smc[];
    const uint32_t sb = smem_u32(smc);
    const int tid = threadIdx.x, wid = tid >> 5, lid = tid & 31;

    for (int i = tid; i < 12288; i += 256) {      // (n, k/2)
        int n = i >> 5, k = (i & 31) * 2;
        int t = n >> 6, h = n & 63;
        int base = (t >= 3) ? 64 : 0;
        int c = t - (t >= 3 ? 3 : 0);
        int m0 = (base + k) * 64 + h;
        int m1 = m0 + 64;
        float v0 = (c == 2) ? b3[m0] : W3[m0 * 2 + c];
        float v1 = (c == 2) ? b3[m1] : W3[m1 * 2 + c];
        __nv_bfloat16 hx = __float2bfloat16(v0);
        __nv_bfloat16 hy = __float2bfloat16(v1);
        __nv_bfloat16 lx = __float2bfloat16(v0 - __bfloat162float(hx));
        __nv_bfloat16 ly = __float2bfloat16(v1 - __bfloat162float(hy));
        uint32_t off = tb64(n, k);
        __nv_bfloat162 th; th.x = hx; th.y = hy;
        __nv_bfloat162 tl; tl.x = lx; tl.y = ly;
        *(__nv_bfloat162*)(smc + PC_BH + off) = th;
        *(__nv_bfloat162*)(smc + PC_BL + off) = tl;
    }
    __syncthreads();

    const int ar  = (lid & 7) + ((lid >> 3) & 1) * 8;
    const int aku = lid >> 4;
    const int br  = (lid & 7) + ((lid >> 4) << 3);
    const int bku = (lid >> 3) & 1;

    const int n0 = blockIdx.x * NPB;
    for (int ni = 0; ni < NPB; ni++) {
        const int node = n0 + ni;
        if (node >= NN) break;

        {
            const float* xp = g_out1 + (size_t)node * 6144;
            for (int i = tid; i < 3072; i += 256) {
                int r = i >> 5, k = (i & 31) * 2;
                float2 v = *(const float2*)(xp + r * 64 + k);
                __nv_bfloat16 hx = __float2bfloat16(v.x);
                __nv_bfloat16 hy = __float2bfloat16(v.y);
                __nv_bfloat16 lx = __float2bfloat16(v.x - __bfloat162float(hx));
                __nv_bfloat16 ly = __float2bfloat16(v.y - __bfloat162float(hy));
                uint32_t off = tb64(r, k);
                __nv_bfloat162 th; th.x = hx; th.y = hy;
                __nv_bfloat162 tl; tl.x = lx; tl.y = ly;
                *(__nv_bfloat162*)(smc + PC_XH + off) = th;
                *(__nv_bfloat162*)(smc + PC_XL + off) = tl;
            }
        }
        __syncthreads();

        if (wid < 6) {
            const int mw = wid >> 1, nw = wid & 1;
            const int arow0 = mw * 32 + ar;
            const int arow1 = arow0 + 16;
            const uint32_t ab0 = (uint32_t)arow0 * 128u, ax0 = (uint32_t)(arow0 & 7);
            const uint32_t ab1 = (uint32_t)arow1 * 128u, ax1 = (uint32_t)(arow1 & 7);

            #pragma unroll
            for (int t = 0; t < 6; t++) {
                float acc[2][4][4];
                #pragma unroll
                for (int a = 0; a < 2; a++)
                    #pragma unroll
                    for (int b = 0; b < 4; b++)
                        #pragma unroll
                        for (int c = 0; c < 4; c++) acc[a][b][c] = 0.0f;

                const int brow0 = t * 64 + nw * 32 + br;
                const int brow1 = brow0 + 16;
                const uint32_t bb0 = (uint32_t)brow0 * 128u, bx0 = (uint32_t)(brow0 & 7);
                const uint32_t bb1 = (uint32_t)brow1 * 128u, bx1 = (uint32_t)(brow1 & 7);

                #pragma unroll
                for (int sp = 0; sp < 3; sp++) {
                    const uint32_t Ab = sb + (sp == 2 ? PC_XL : PC_XH);
                    const uint32_t Bb = sb + (sp == 1 ? PC_BL : PC_BH);
                    #pragma unroll
                    for (int ks = 0; ks < 4; ks++) {
                        const uint32_t kb = (uint32_t)(ks * 2);
                        uint32_t af0[4], af1[4], bf0[4], bf1[4];
                        ldmx4(af0, Ab + ab0 + (((kb + aku) ^ ax0) << 4));
                        ldmx4(af1, Ab + ab1 + (((kb + aku) ^ ax1) << 4));
                        ldmx4(bf0, Bb + bb0 + (((kb + bku) ^ bx0) << 4));
                        ldmx4(bf1, Bb + bb1 + (((kb + bku) ^ bx1) << 4));
                        mma16816(acc[0][0], af0, bf0);
                        mma16816(acc[0][1], af0, bf0 + 2);
                        mma16816(acc[0][2], af0, bf1);
                        mma16816(acc[0][3], af0, bf1 + 2);
                        mma16816(acc[1][0], af1, bf0);
                        mma16816(acc[1][1], af1, bf0 + 2);
                        mma16816(acc[1][2], af1, bf1);
                        mma16816(acc[1][3], af1, bf1 + 2);
                    }
                }
                __half* yp = g_Yh + ((size_t)node * 6 + t) * 6144;
                const int g = lid >> 2, c2 = (lid & 3) * 2;
                #pragma unroll
                for (int mt = 0; mt < 2; mt++) {
                    const int r0 = mw * 32 + mt * 16 + g;
                    const int r1 = r0 + 8;
                    #pragma unroll
                    for (int nt = 0; nt < 4; nt++) {
                        const int c0 = nw * 32 + nt * 8 + c2;
                        *(__half2*)(yp + r0 * 64 + c0) =
                            __floats2half2_rn(acc[mt][nt][0], acc[mt][nt][1]);
                        *(__half2*)(yp + r1 * 64 + c0) =
                            __floats2half2_rn(acc[mt][nt][2], acc[mt][nt][3]);
                    }
                }
            }
        }
        __syncthreads();
    }
}

// ---------------------------------------------------------------------------
// Edge gather kernel: one block per DST node.
//   - scan edge list for dst == blockIdx.x (plus self loop)
//   - stage A-planes(dst) in smem once; accumulate agg in smem f32
//   - per edge: MLP -> alpha(A_smem + B_global) -> softmax -> msg accum
//   - single write of agg (no atomics, no zero pass)
// smem bytes:
//   cnt @0, srcs[96] @16, featd @512(256B), hdn @768, hdn2 @832, featsrc @896
//   A planes fp16 @2048  (36864)
//   agg  f32     @38912 (24576)
//   alpha f32    @63488 (24576)   total 88064
// ---------------------------------------------------------------------------
#define EG_SRCS   16
#define EG_FEATD  512
#define EG_HDN    768
#define EG_HDN2   832
#define EG_FEATS  896
#define EG_A      2048
#define EG_AGG    38912
#define EG_ALPHA  63488
#define EG_SMEM   88064
#define MAX_DEG   95

extern "C" __global__ void __launch_bounds__(256)
edge_gather_kernel(const float* __restrict__ features,
                   const int* __restrict__ ei,
                   const float* __restrict__ W1,
                   const float* __restrict__ b1,
                   const float* __restrict__ W2,
                   const float* __restrict__ b2)
{
    extern __shared__ char smc[];
    int*   cnt_s   = (int*)smc;
    int*   srcs    = (int*)(smc + EG_SRCS);
    float* featd   = (float*)(smc + EG_FEATD);
    float* hdn     = (float*)(smc + EG_HDN);
    float* hdn2    = (float*)(smc + EG_HDN2);
    float* featsrc = (float*)(smc + EG_FEATS);
    const uint2* As = (const uint2*)(smc + EG_A);
    float* agg_s   = (float*)(smc + EG_AGG);
    float* al      = (float*)(smc + EG_ALPHA);

    const int tid = threadIdx.x;
    const int dst = blockIdx.x;

    if (tid == 0) {
        cnt_s[0] = 1;
        srcs[0] = dst;          // self loop
    }
    if (tid < 64) featd[tid] = features[dst * 64 + tid];

    // stage A planes (dst, planes 0..2) : 36864 B = 2304 uint4
    {
        const uint4* ap = (const uint4*)(g_Yh + (size_t)dst * 36864);
        uint4* dp = (uint4*)(smc + EG_A);
        for (int i = tid; i < 2304; i += 256) dp[i] = ap[i];
    }
    // zero agg
    {
        float4 z = make_float4(0.f, 0.f, 0.f, 0.f);
        for (int i = tid; i < 1536; i += 256) ((float4*)agg_s)[i] = z;
    }
    __syncthreads();

    // scan edge list for this dst
    for (int i = tid; i < EE; i += 256) {
        if (ei[EE + i] == dst) {
            int p = atomicAdd(cnt_s, 1);
            if (p < MAX_DEG) srcs[p] = ei[i];
        }
    }
    __syncthreads();
    int cnt = cnt_s[0];
    if (cnt > MAX_DEG) cnt = MAX_DEG;

    for (int g = 0; g < cnt; g++) {
        const int src = srcs[g];
        if (tid < 64) featsrc[tid] = features[src * 64 + tid];
        __syncthreads();

        if (tid < 16) {
            float acc = b1[tid];
            const float* wrow = W1 + tid * 128;
            #pragma unroll 8
            for (int k = 0; k < 64; k++)  acc = fmaf(featd[k],   wrow[k],      acc);
            #pragma unroll 8
            for (int k = 0; k < 64; k++)  acc = fmaf(featsrc[k], wrow[64 + k], acc);
            hdn[tid] = fsig(acc);
        }
        __syncthreads();
        if (tid < 2) {
            float acc = b2[tid];
            const float* wrow = W2 + tid * 16;
            #pragma unroll
            for (int k = 0; k < 16; k++) acc = fmaf(hdn[k], wrow[k], acc);
            hdn2[tid] = fsig(acc);
        }
        __syncthreads();

        const float h0 = hdn2[0], h1 = hdn2[1];
        const uint2* Bs = (const uint2*)(g_Yh + (size_t)src * 36864 + 18432);

        #pragma unroll 2
        for (int i = tid; i < 1536; i += 256) {
            float4 a0 = h4_to_f4(As[i]);
            float4 a1 = h4_to_f4(As[1536 + i]);
            float4 a2 = h4_to_f4(As[3072 + i]);
            float4 b0 = h4_to_f4(Bs[i]);
            float4 b1v = h4_to_f4(Bs[1536 + i]);
            float4 b2v = h4_to_f4(Bs[3072 + i]);
            float4 v;
            v.x = fmaf(h0, a0.x + b0.x, fmaf(h1, a1.x + b1v.x, a2.x + b2v.x));
            v.y = fmaf(h0, a0.y + b0.y, fmaf(h1, a1.y + b1v.y, a2.y + b2v.y));
            v.z = fmaf(h0, a0.z + b0.z, fmaf(h1, a1.z + b1v.z, a2.z + b2v.z));
            v.w = fmaf(h0, a0.w + b0.w, fmaf(h1, a1.w + b1v.w, a2.w + b2v.w));
            v.x = v.x > 0.f ? v.x : 0.01f * v.x;
            v.y = v.y > 0.f ? v.y : 0.01f * v.y;
            v.z = v.z > 0.f ? v.z : 0.01f * v.z;
            v.w = v.w > 0.f ? v.w : 0.01f * v.w;
            int m = i >> 4, c4 = i & 15;
            *(float4*)&al[m * 64 + 4 * (c4 ^ (m & 15))] = v;
        }
        __syncthreads();

        // softmax over batch (8) + msg accumulate into smem agg
        if (tid < 192) {
            const int l = tid >> 4, h4 = tid & 15;
            float4 a[8];
            float4 mx = make_float4(-1e30f, -1e30f, -1e30f, -1e30f);
            #pragma unroll
            for (int b = 0; b < 8; b++) {
                int m = b * 12 + l;
                a[b] = *(const float4*)&al[m * 64 + 4 * (h4 ^ (m & 15))];
                mx.x = fmaxf(mx.x, a[b].x); mx.y = fmaxf(mx.y, a[b].y);
                mx.z = fmaxf(mx.z, a[b].z); mx.w = fmaxf(mx.w, a[b].w);
            }
            float4 ssum = make_float4(0.f, 0.f, 0.f, 0.f);
            #pragma unroll
            for (int b = 0; b < 8; b++) {
                a[b].x = fexp2(1.4426950408889634f * (a[b].x - mx.x));
                a[b].y = fexp2(1.4426950408889634f * (a[b].y - mx.y));
                a[b].z = fexp2(1.4426950408889634f * (a[b].z - mx.z));
                a[b].w = fexp2(1.4426950408889634f * (a[b].w - mx.w));
                ssum.x += a[b].x; ssum.y += a[b].y; ssum.z += a[b].z; ssum.w += a[b].w;
            }
            float4 inv = make_float4(frcp(ssum.x), frcp(ssum.y), frcp(ssum.z), frcp(ssum.w));
            const uint2* xj = (const uint2*)(g_out1h + (size_t)src * 6144);
            #pragma unroll
            for (int b = 0; b < 8; b++) {
                int m = b * 12 + l;
                float4 sj = h4_to_f4(xj[m * 16 + h4]);
                float* ap = agg_s + m * 64 + h4 * 4;
                ap[0] += a[b].x * inv.x * sj.x;
                ap[1] += a[b].y * inv.y * sj.y;
                ap[2] += a[b].z * inv.z * sj.z;
                ap[3] += a[b].w * inv.w * sj.w;
            }
        }
        __syncthreads();
    }

    // write agg once
    {
        float4* op = (float4*)(g_agg + (size_t)dst * 6144);
        const float4* ip = (const float4*)agg_s;
        for (int i = tid; i < 1536; i += 256) op[i] = ip[i];
    }
}

// ---------------------------------------------------------------------------
// GRU2 (R13 proven version: 4 seqs/thread, 16 seqs/block)
// ---------------------------------------------------------------------------
extern "C" __global__ void gru2_kernel(const float* __restrict__ Wih,
                                       const float* __restrict__ Whh,
                                       const float* __restrict__ bih,
                                       const float* __restrict__ bhh,
                                       float* __restrict__ h2_out)
{
    extern __shared__ float sm[];
    float* wT   = sm;
    float* h_sh = sm + 24640;
    float* x_sh = sm + 24640 + 1024;

    const int tid = threadIdx.x;
    const int grp = tid >> 6;
    const int j   = tid & 63;

    for (int idx = tid; idx < 12288; idx += 256) {
        int g = idx >> 6, k = idx & 63;
        int m = g >> 6, jj = g & 63;
        wT[k * 385 + m * 64 + jj]       = Wih[idx];
        wT[k * 385 + 192 + m * 64 + jj] = Whh[idx];
    }

    float br = bih[j], bz = bih[64 + j], bn = bih[128 + j];
    float cr = bhh[j], cz = bhh[64 + j], cn = bhh[128 + j];

    float h[4] = {0.f, 0.f, 0.f, 0.f};
    const int s0 = blockIdx.x * 16 + grp * 4;
    const float* xg = g_agg + (size_t)s0 * 768 + j;

    for (int l = 0; l < LL; l++) {
        float4 xv;
        xv.x = fmaxf(xg[0 * 768 + l * 64], 0.0f);
        xv.y = fmaxf(xg[1 * 768 + l * 64], 0.0f);
        xv.z = fmaxf(xg[2 * 768 + l * 64], 0.0f);
        xv.w = fmaxf(xg[3 * 768 + l * 64], 0.0f);
        *(float4*)&x_sh[grp * 256 + j * 4] = xv;
        *(float4*)&h_sh[grp * 256 + j * 4] = make_float4(h[0], h[1], h[2], h[3]);
        __syncthreads();

        float gr[4], gz[4], gn[4];
        #pragma unroll
        for (int s = 0; s < 4; s++) { gr[s] = br + cr; gz[s] = bz + cz; gn[s] = bn; }
        float ghn[4] = {cn, cn, cn, cn};

        const float* wp = wT + j;
        const float* hp = h_sh + grp * 256;
        const float* xp = x_sh + grp * 256;
        #pragma unroll 2
        for (int k = 0; k < 64; k++) {
            float wi0 = wp[k * 385];
            float wi1 = wp[k * 385 + 64];
            float wi2 = wp[k * 385 + 128];
            float wh0 = wp[k * 385 + 192];
            float wh1 = wp[k * 385 + 256];
            float wh2 = wp[k * 385 + 320];
            float4 xk = *(const float4*)&xp[k * 4];
            float4 hk = *(const float4*)&hp[k * 4];
            gr[0] = fmaf(xk.x, wi0, gr[0]); gz[0] = fmaf(xk.x, wi1, gz[0]); gn[0] = fmaf(xk.x, wi2, gn[0]);
            gr[0] = fmaf(hk.x, wh0, gr[0]); gz[0] = fmaf(hk.x, wh1, gz[0]); ghn[0] = fmaf(hk.x, wh2, ghn[0]);
            gr[1] = fmaf(xk.y, wi0, gr[1]); gz[1] = fmaf(xk.y, wi1, gz[1]); gn[1] = fmaf(xk.y, wi2, gn[1]);
            gr[1] = fmaf(hk.y, wh0, gr[1]); gz[1] = fmaf(hk.y, wh1, gz[1]); ghn[1] = fmaf(hk.y, wh2, ghn[1]);
            gr[2] = fmaf(xk.z, wi0, gr[2]); gz[2] = fmaf(xk.z, wi1, gz[2]); gn[2] = fmaf(xk.z, wi2, gn[2]);
            gr[2] = fmaf(hk.z, wh0, gr[2]); gz[2] = fmaf(hk.z, wh1, gz[2]); ghn[2] = fmaf(hk.z, wh2, ghn[2]);
            gr[3] = fmaf(xk.w, wi0, gr[3]); gz[3] = fmaf(xk.w, wi1, gz[3]); gn[3] = fmaf(xk.w, wi2, gn[3]);
            gr[3] = fmaf(hk.w, wh0, gr[3]); gz[3] = fmaf(hk.w, wh1, gz[3]); ghn[3] = fmaf(hk.w, wh2, ghn[3]);
        }
        #pragma unroll
        for (int s = 0; s < 4; s++) {
            float r = fsig(gr[s]);
            float z = fsig(gz[s]);
            float n = ftanh(fmaf(r, ghn[s], gn[s]));
            h[s] = fmaf(z, h[s] - n, n);
        }
        __syncthreads();
    }
    #pragma unroll
    for (int s = 0; s < 4; s++)
        h2_out[(s0 + s) * 64 + j] = h[s];
}

// ---------------------------------------------------------------------------

static const int GRU1_SMEM = (12352 + 1024 + 384) * 4;
static const int GRU2_SMEM = (24640 + 1024 + 1024) * 4;

extern "C" void kernel_launch(void* const* d_in, const int* in_sizes, int n_in,
                              void* d_out, int out_size)
{
    const float* data     = (const float*)d_in[0];
    const float* features = (const float*)d_in[1];
    const int*   ei       = (const int*)  d_in[2];
    const float* Wih1     = (const float*)d_in[3];
    const float* Whh1     = (const float*)d_in[4];
    const float* bih1     = (const float*)d_in[5];
    const float* bhh1     = (const float*)d_in[6];
    const float* W1       = (const float*)d_in[7];
    const float* b1       = (const float*)d_in[8];
    const float* W2       = (const float*)d_in[9];
    const float* b2       = (const float*)d_in[10];
    const float* W3       = (const float*)d_in[11];
    const float* b3       = (const float*)d_in[12];
    const float* Wih2     = (const float*)d_in[13];
    const float* Whh2     = (const float*)d_in[14];
    const float* bih2     = (const float*)d_in[15];
    const float* bhh2     = (const float*)d_in[16];
    float* out = (float*)d_out;

    cudaFuncSetAttribute(gru1_kernel, cudaFuncAttributeMaxDynamicSharedMemorySize, GRU1_SMEM);
    cudaFuncSetAttribute(gru2_kernel, cudaFuncAttributeMaxDynamicSharedMemorySize, GRU2_SMEM);
    cudaFuncSetAttribute(precomp_kernel, cudaFuncAttributeMaxDynamicSharedMemorySize, PC_SMEM);
    cudaFuncSetAttribute(edge_gather_kernel, cudaFuncAttributeMaxDynamicSharedMemorySize, EG_SMEM);

    gru1_kernel<<<NSEQ / 16, 256, GRU1_SMEM>>>(data, Wih1, Whh1, bih1, bhh1, out);
    precomp_kernel<<<PRE_GRID, 256, PC_SMEM>>>(W3, b3);
    edge_gather_kernel<<<NN, 256, EG_SMEM>>>(features, ei, W1, b1, W2, b2);
    gru2_kernel<<<NSEQ / 16, 256, GRU2_SMEM>>>(Wih2, Whh2, bih2, bhh2, out + NSEQ * HH);
}

// round 16
// speedup vs baseline: 1.3051x; 1.3051x over previous
#include <cuda_runtime.h>
#include <cuda_bf16.h>
#include <cuda_fp16.h>
#include <cstdint>
#include <stdint.h>
#include <math.h>

#define NN 2000
#define BB 8
#define LL 12
#define DD 2
#define HH 64
#define EE 16000
#define ETOT 18000
#define NSEQ (NN*BB)                 // 16000
#define OUT1_ELEMS (NSEQ*LL*HH)      // 12,288,000
#define NPB 14                       // nodes per precompute block
#define PRE_GRID ((NN + NPB - 1) / NPB)

__device__ float  g_out1[OUT1_ELEMS];
__device__ __half g_out1h[OUT1_ELEMS];              // fp16 mirror for edge msg
__device__ float  g_agg[OUT1_ELEMS];
__device__ __half g_Yh[(size_t)NN * 6 * 96 * 64];   // 147.5 MB fp16 planes

// CSR edge binning (sorted by dst)
__device__ int g_cnt[NN];
__device__ int g_fill[NN];
__device__ int g_base[NN];
__device__ int g_esrc[ETOT];
__device__ int g_edst[ETOT];

// ---------------------------------------------------------------------------
// FMA-only fast math (no MUFU)
// ---------------------------------------------------------------------------
__device__ __forceinline__ float fexp2(float y) {
    y = fminf(fmaxf(y, -125.0f), 125.0f);
    float r = __fadd_rn(y, 12582912.0f);
    int   n = __float_as_int(r) - 0x4B400000;
    float f = __fsub_rn(y, __fsub_rn(r, 12582912.0f));
    float u = f * 0.69314718055994531f;
    float p = fmaf(u, 1.3888889e-3f, 8.3333333e-3f);
    p = fmaf(u, p, 4.1666667e-2f);
    p = fmaf(u, p, 1.6666667e-1f);
    p = fmaf(u, p, 0.5f);
    p = fmaf(u, p, 1.0f);
    p = fmaf(u, p, 1.0f);
    return p * __int_as_float((n + 127) << 23);
}
__device__ __forceinline__ float frcp(float x) {
    float r = __int_as_float(0x7EF311C3 - __float_as_int(x));
    r = r * __fmaf_rn(-x, r, 2.0f);
    r = r * __fmaf_rn(-x, r, 2.0f);
    r = r * __fmaf_rn(-x, r, 2.0f);
    return r;
}
__device__ __forceinline__ float fsig(float x) {
    return frcp(1.0f + fexp2(-1.4426950408889634f * x));
}
__device__ __forceinline__ float ftanh(float x) {
    float e = fexp2(2.8853900817779268f * x);
    return fmaf(-2.0f, frcp(1.0f + e), 1.0f);
}

// ---------------------------------------------------------------------------
// mma.sync / ldmatrix helpers (sm_80+ path, legal on sm_103)
// ---------------------------------------------------------------------------
__device__ __forceinline__ uint32_t smem_u32(const void* p) {
    uint32_t a;
    asm("{ .reg .u64 t; cvta.to.shared.u64 t, %1; cvt.u32.u64 %0, t; }"
        : "=r"(a) : "l"(p));
    return a;
}
__device__ __forceinline__ void ldmx4(uint32_t* r, uint32_t addr) {
    asm volatile("ldmatrix.sync.aligned.m8n8.x4.shared.b16 {%0,%1,%2,%3}, [%4];"
                 : "=r"(r[0]), "=r"(r[1]), "=r"(r[2]), "=r"(r[3]) : "r"(addr));
}
__device__ __forceinline__ void mma16816(float* d, const uint32_t* a, const uint32_t* b) {
    asm volatile("mma.sync.aligned.m16n8k16.row.col.f32.bf16.bf16.f32 "
                 "{%0,%1,%2,%3}, {%4,%5,%6,%7}, {%8,%9}, {%0,%1,%2,%3};"
                 : "+f"(d[0]), "+f"(d[1]), "+f"(d[2]), "+f"(d[3])
                 : "r"(a[0]), "r"(a[1]), "r"(a[2]), "r"(a[3]),
                   "r"(b[0]), "r"(b[1]));
}
// tiles with 64 bf16 per row (128 B = 8 x 16B units), unit ^= (row&7)
__device__ __forceinline__ uint32_t tb64(int row, int k) {
    return (uint32_t)(row * 8 + ((k >> 3) ^ (row & 7))) * 16u
         + (uint32_t)(k & 7) * 2u;
}
__device__ __forceinline__ float4 h4_to_f4(uint2 u) {
    float2 lo = __half22float2(*(__half2*)&u.x);
    float2 hi = __half22float2(*(__half2*)&u.y);
    float4 r; r.x = lo.x; r.y = lo.y; r.z = hi.x; r.w = hi.y;
    return r;
}

// ---------------------------------------------------------------------------
// Edge binning kernels
// ---------------------------------------------------------------------------
extern "C" __global__ void bin_zero_kernel()
{
    int i = blockIdx.x * blockDim.x + threadIdx.x;
    if (i < NN) { g_cnt[i] = 0; g_fill[i] = 0; }
}
extern "C" __global__ void bin_count_kernel(const int* __restrict__ ei)
{
    int i = blockIdx.x * blockDim.x + threadIdx.x;
    if (i < EE) atomicAdd(&g_cnt[ei[EE + i]], 1);
}
extern "C" __global__ void bin_scan_kernel()
{
    __shared__ int warp_sums[32];
    const int t = threadIdx.x;
    const int i0 = 2 * t, i1 = 2 * t + 1;
    int c0 = (i0 < NN) ? g_cnt[i0] + 1 : 0;   // +1 = self loop slot
    int c1 = (i1 < NN) ? g_cnt[i1] + 1 : 0;
    int tot = c0 + c1;
    const int lane = t & 31, wid = t >> 5;
    int v = tot;
    #pragma unroll
    for (int o = 1; o < 32; o <<= 1) {
        int u = __shfl_up_sync(0xFFFFFFFFu, v, o);
        if (lane >= o) v += u;
    }
    if (lane == 31) warp_sums[wid] = v;
    __syncthreads();
    if (wid == 0) {
        int w = warp_sums[lane];
        #pragma unroll
        for (int o = 1; o < 32; o <<= 1) {
            int u = __shfl_up_sync(0xFFFFFFFFu, w, o);
            if (lane >= o) w += u;
        }
        warp_sums[lane] = w;
    }
    __syncthreads();
    int ex = v - tot + (wid > 0 ? warp_sums[wid - 1] : 0);
    if (i0 < NN) g_base[i0] = ex;
    if (i1 < NN) g_base[i1] = ex + c0;
}
extern "C" __global__ void bin_fill_kernel(const int* __restrict__ ei)
{
    int i = blockIdx.x * blockDim.x + threadIdx.x;
    if (i < EE) {
        int d = ei[EE + i];
        int pos = g_base[d] + atomicAdd(&g_fill[d], 1);
        g_esrc[pos] = ei[i];
        g_edst[pos] = d;
    }
    if (i < NN) {                       // self loop at last slot of bin
        int pos = g_base[i] + g_cnt[i];
        g_esrc[pos] = i;
        g_edst[pos] = i;
    }
}

// ---------------------------------------------------------------------------
// GRU1: 4 seqs/thread (proven) + fp16 mirror store
// ---------------------------------------------------------------------------
extern "C" __global__ void gru1_kernel(const float* __restrict__ data,
                                       const float* __restrict__ Wih,
                                       const float* __restrict__ Whh,
                                       const float* __restrict__ bih,
                                       const float* __restrict__ bhh,
                                       float* __restrict__ h1_out)
{
    extern __shared__ float sm[];
    float* whhT = sm;
    float* h_sh = sm + 12352;
    float* x_sh = sm + 12352 + 1024;

    const int tid = threadIdx.x;
    const int grp = tid >> 6;
    const int j   = tid & 63;

    for (int idx = tid; idx < 12288; idx += 256) {
        int g = idx >> 6, k = idx & 63;
        int m = g >> 6, jj = g & 63;
        whhT[k * 193 + m * 64 + jj] = Whh[idx];
    }
    for (int idx = tid; idx < 384; idx += 256)
        x_sh[idx] = data[(size_t)blockIdx.x * 384 + idx];

    float wr0 = Wih[j * 2],        wr1 = Wih[j * 2 + 1];
    float wz0 = Wih[(64 + j) * 2], wz1 = Wih[(64 + j) * 2 + 1];
    float wn0 = Wih[(128 + j)* 2], wn1 = Wih[(128 + j)* 2 + 1];
    float br = bih[j], bz = bih[64 + j], bn = bih[128 + j];
    float cr = bhh[j], cz = bhh[64 + j], cn = bhh[128 + j];

    float h[4] = {0.f, 0.f, 0.f, 0.f};
    const int s0 = blockIdx.x * 16 + grp * 4;
    float*  outb = g_out1  + (size_t)s0 * 768 + j;
    __half* outh = g_out1h + (size_t)s0 * 768 + j;

    for (int l = 0; l < LL; l++) {
        *(float4*)&h_sh[grp * 256 + j * 4] = make_float4(h[0], h[1], h[2], h[3]);
        __syncthreads();

        float ghr[4], ghz[4], ghn[4];
        #pragma unroll
        for (int s = 0; s < 4; s++) { ghr[s] = cr; ghz[s] = cz; ghn[s] = cn; }

        const float* wp = whhT + j;
        const float* hp = h_sh + grp * 256;
        #pragma unroll 4
        for (int k = 0; k < 64; k++) {
            float w0 = wp[k * 193];
            float w1 = wp[k * 193 + 64];
            float w2 = wp[k * 193 + 128];
            float4 hv = *(const float4*)&hp[k * 4];
            ghr[0] = fmaf(hv.x, w0, ghr[0]); ghz[0] = fmaf(hv.x, w1, ghz[0]); ghn[0] = fmaf(hv.x, w2, ghn[0]);
            ghr[1] = fmaf(hv.y, w0, ghr[1]); ghz[1] = fmaf(hv.y, w1, ghz[1]); ghn[1] = fmaf(hv.y, w2, ghn[1]);
            ghr[2] = fmaf(hv.z, w0, ghr[2]); ghz[2] = fmaf(hv.z, w1, ghz[2]); ghn[2] = fmaf(hv.z, w2, ghn[2]);
            ghr[3] = fmaf(hv.w, w0, ghr[3]); ghz[3] = fmaf(hv.w, w1, ghz[3]); ghn[3] = fmaf(hv.w, w2, ghn[3]);
        }
        #pragma unroll
        for (int s = 0; s < 4; s++) {
            float x0 = x_sh[(grp * 4 + s) * 24 + l * 2];
            float x1 = x_sh[(grp * 4 + s) * 24 + l * 2 + 1];
            float gir = fmaf(x1, wr1, fmaf(x0, wr0, br));
            float giz = fmaf(x1, wz1, fmaf(x0, wz0, bz));
            float gin = fmaf(x1, wn1, fmaf(x0, wn0, bn));
            float r = fsig(gir + ghr[s]);
            float z = fsig(giz + ghz[s]);
            float n = ftanh(fmaf(r, ghn[s], gin));
            h[s] = fmaf(z, h[s] - n, n);
            outb[s * 768 + l * 64] = h[s];
            outh[s * 768 + l * 64] = __float2half(h[s]);
        }
        __syncthreads();
    }
    #pragma unroll
    for (int s = 0; s < 4; s++)
        h1_out[(s0 + s) * 64 + j] = h[s];
}

// ---------------------------------------------------------------------------
extern "C" __global__ void zero_agg_kernel()
{
    float4 z = make_float4(0.f, 0.f, 0.f, 0.f);
    for (int i = blockIdx.x * blockDim.x + threadIdx.x; i < OUT1_ELEMS / 4;
         i += gridDim.x * blockDim.x)
        ((float4*)g_agg)[i] = z;
}

// ---------------------------------------------------------------------------
// Precompute kernel (unchanged, proven): per node n, 6 fp16 planes
// ---------------------------------------------------------------------------
#define PC_BH 0
#define PC_BL 49152
#define PC_XH 98304
#define PC_XL 110592
#define PC_SMEM 122880

extern "C" __global__ void __launch_bounds__(256, 1)
precomp_kernel(const float* __restrict__ W3, const float* __restrict__ b3)
{
    extern __shared__ char smc[];
    const uint32_t sb = smem_u32(smc);
    const int tid = threadIdx.x, wid = tid >> 5, lid = tid & 31;

    for (int i = tid; i < 12288; i += 256) {      // (n, k/2)
        int n = i >> 5, k = (i & 31) * 2;
        int t = n >> 6, h = n & 63;
        int base = (t >= 3) ? 64 : 0;
        int c = t - (t >= 3 ? 3 : 0);
        int m0 = (base + k) * 64 + h;
        int m1 = m0 + 64;
        float v0 = (c == 2) ? b3[m0] : W3[m0 * 2 + c];
        float v1 = (c == 2) ? b3[m1] : W3[m1 * 2 + c];
        __nv_bfloat16 hx = __float2bfloat16(v0);
        __nv_bfloat16 hy = __float2bfloat16(v1);
        __nv_bfloat16 lx = __float2bfloat16(v0 - __bfloat162float(hx));
        __nv_bfloat16 ly = __float2bfloat16(v1 - __bfloat162float(hy));
        uint32_t off = tb64(n, k);
        __nv_bfloat162 th; th.x = hx; th.y = hy;
        __nv_bfloat162 tl; tl.x = lx; tl.y = ly;
        *(__nv_bfloat162*)(smc + PC_BH + off) = th;
        *(__nv_bfloat162*)(smc + PC_BL + off) = tl;
    }
    __syncthreads();

    const int ar  = (lid & 7) + ((lid >> 3) & 1) * 8;
    const int aku = lid >> 4;
    const int br  = (lid & 7) + ((lid >> 4) << 3);
    const int bku = (lid >> 3) & 1;

    const int n0 = blockIdx.x * NPB;
    for (int ni = 0; ni < NPB; ni++) {
        const int node = n0 + ni;
        if (node >= NN) break;

        {
            const float* xp = g_out1 + (size_t)node * 6144;
            for (int i = tid; i < 3072; i += 256) {
                int r = i >> 5, k = (i & 31) * 2;
                float2 v = *(const float2*)(xp + r * 64 + k);
                __nv_bfloat16 hx = __float2bfloat16(v.x);
                __nv_bfloat16 hy = __float2bfloat16(v.y);
                __nv_bfloat16 lx = __float2bfloat16(v.x - __bfloat162float(hx));
                __nv_bfloat16 ly = __float2bfloat16(v.y - __bfloat162float(hy));
                uint32_t off = tb64(r, k);
                __nv_bfloat162 th; th.x = hx; th.y = hy;
                __nv_bfloat162 tl; tl.x = lx; tl.y = ly;
                *(__nv_bfloat162*)(smc + PC_XH + off) = th;
                *(__nv_bfloat162*)(smc + PC_XL + off) = tl;
            }
        }
        __syncthreads();

        if (wid < 6) {
            const int mw = wid >> 1, nw = wid & 1;
            const int arow0 = mw * 32 + ar;
            const int arow1 = arow0 + 16;
            const uint32_t ab0 = (uint32_t)arow0 * 128u, ax0 = (uint32_t)(arow0 & 7);
            const uint32_t ab1 = (uint32_t)arow1 * 128u, ax1 = (uint32_t)(arow1 & 7);

            #pragma unroll
            for (int t = 0; t < 6; t++) {
                float acc[2][4][4];
                #pragma unroll
                for (int a = 0; a < 2; a++)
                    #pragma unroll
                    for (int b = 0; b < 4; b++)
                        #pragma unroll
                        for (int c = 0; c < 4; c++) acc[a][b][c] = 0.0f;

                const int brow0 = t * 64 + nw * 32 + br;
                const int brow1 = brow0 + 16;
                const uint32_t bb0 = (uint32_t)brow0 * 128u, bx0 = (uint32_t)(brow0 & 7);
                const uint32_t bb1 = (uint32_t)brow1 * 128u, bx1 = (uint32_t)(brow1 & 7);

                #pragma unroll
                for (int sp = 0; sp < 3; sp++) {
                    const uint32_t Ab = sb + (sp == 2 ? PC_XL : PC_XH);
                    const uint32_t Bb = sb + (sp == 1 ? PC_BL : PC_BH);
                    #pragma unroll
                    for (int ks = 0; ks < 4; ks++) {
                        const uint32_t kb = (uint32_t)(ks * 2);
                        uint32_t af0[4], af1[4], bf0[4], bf1[4];
                        ldmx4(af0, Ab + ab0 + (((kb + aku) ^ ax0) << 4));
                        ldmx4(af1, Ab + ab1 + (((kb + aku) ^ ax1) << 4));
                        ldmx4(bf0, Bb + bb0 + (((kb + bku) ^ bx0) << 4));
                        ldmx4(bf1, Bb + bb1 + (((kb + bku) ^ bx1) << 4));
                        mma16816(acc[0][0], af0, bf0);
                        mma16816(acc[0][1], af0, bf0 + 2);
                        mma16816(acc[0][2], af0, bf1);
                        mma16816(acc[0][3], af0, bf1 + 2);
                        mma16816(acc[1][0], af1, bf0);
                        mma16816(acc[1][1], af1, bf0 + 2);
                        mma16816(acc[1][2], af1, bf1);
                        mma16816(acc[1][3], af1, bf1 + 2);
                    }
                }
                __half* yp = g_Yh + ((size_t)node * 6 + t) * 6144;
                const int g = lid >> 2, c2 = (lid & 3) * 2;
                #pragma unroll
                for (int mt = 0; mt < 2; mt++) {
                    const int r0 = mw * 32 + mt * 16 + g;
                    const int r1 = r0 + 8;
                    #pragma unroll
                    for (int nt = 0; nt < 4; nt++) {
                        const int c0 = nw * 32 + nt * 8 + c2;
                        *(__half2*)(yp + r0 * 64 + c0) =
                            __floats2half2_rn(acc[mt][nt][0], acc[mt][nt][1]);
                        *(__half2*)(yp + r1 * 64 + c0) =
                            __floats2half2_rn(acc[mt][nt][2], acc[mt][nt][3]);
                    }
                }
            }
        }
        __syncthreads();
    }
}

// ---------------------------------------------------------------------------
// Edge streaming kernel (R14 proven body; dst-sorted edge order for L2 reuse)
// ---------------------------------------------------------------------------
#define ES_SMEM (1024 + 24576)

extern "C" __global__ void __launch_bounds__(256)
edge_stream_kernel(const float* __restrict__ features,
                   const float* __restrict__ W1,
                   const float* __restrict__ b1,
                   const float* __restrict__ W2,
                   const float* __restrict__ b2)
{
    extern __shared__ char smc[];
    float* feats = (float*)(smc + 64);
    float* hdn   = (float*)(smc + 576);
    float* hdn2  = (float*)(smc + 640);
    float* al    = (float*)(smc + 1024);

    const int tid = threadIdx.x;
    const int e = blockIdx.x;
    const int src = g_esrc[e];
    const int dst = g_edst[e];

    if (tid < 128)
        feats[tid] = (tid < 64) ? features[dst * 64 + tid]
                                : features[src * 64 + (tid - 64)];
    __syncthreads();

    if (tid < 16) {
        float acc = b1[tid];
        const float* wrow = W1 + tid * 128;
        #pragma unroll 8
        for (int k = 0; k < 128; k++) acc = fmaf(feats[k], wrow[k], acc);
        hdn[tid] = fsig(acc);
    }
    __syncthreads();
    if (tid < 2) {
        float acc = b2[tid];
        const float* wrow = W2 + tid * 16;
        #pragma unroll
        for (int k = 0; k < 16; k++) acc = fmaf(hdn[k], wrow[k], acc);
        hdn2[tid] = fsig(acc);
    }
    __syncthreads();

    const float h0 = hdn2[0], h1 = hdn2[1];
    const uint2* Ad = (const uint2*)(g_Yh + (size_t)dst * 36864);          // planes 0..2
    const uint2* Bs = (const uint2*)(g_Yh + (size_t)src * 36864 + 18432);  // planes 3..5

    #pragma unroll 2
    for (int i = tid; i < 1536; i += 256) {
        float4 a0 = h4_to_f4(Ad[i]);
        float4 a1 = h4_to_f4(Ad[1536 + i]);
        float4 a2 = h4_to_f4(Ad[3072 + i]);
        float4 b0 = h4_to_f4(Bs[i]);
        float4 b1v = h4_to_f4(Bs[1536 + i]);
        float4 b2v = h4_to_f4(Bs[3072 + i]);
        float4 v;
        v.x = fmaf(h0, a0.x + b0.x, fmaf(h1, a1.x + b1v.x, a2.x + b2v.x));
        v.y = fmaf(h0, a0.y + b0.y, fmaf(h1, a1.y + b1v.y, a2.y + b2v.y));
        v.z = fmaf(h0, a0.z + b0.z, fmaf(h1, a1.z + b1v.z, a2.z + b2v.z));
        v.w = fmaf(h0, a0.w + b0.w, fmaf(h1, a1.w + b1v.w, a2.w + b2v.w));
        v.x = v.x > 0.f ? v.x : 0.01f * v.x;
        v.y = v.y > 0.f ? v.y : 0.01f * v.y;
        v.z = v.z > 0.f ? v.z : 0.01f * v.z;
        v.w = v.w > 0.f ? v.w : 0.01f * v.w;
        int m = i >> 4, c4 = i & 15;
        *(float4*)&al[m * 64 + 4 * (c4 ^ (m & 15))] = v;
    }
    __syncthreads();

    // ---- softmax over batch (8) + msg + vector atomic scatter ----
    if (tid < 192) {
        const int l = tid >> 4, h4 = tid & 15;
        float4 a[8];
        float4 mx = make_float4(-1e30f, -1e30f, -1e30f, -1e30f);
        #pragma unroll
        for (int b = 0; b < 8; b++) {
            int m = b * 12 + l;
            a[b] = *(const float4*)&al[m * 64 + 4 * (h4 ^ (m & 15))];
            mx.x = fmaxf(mx.x, a[b].x); mx.y = fmaxf(mx.y, a[b].y);
            mx.z = fmaxf(mx.z, a[b].z); mx.w = fmaxf(mx.w, a[b].w);
        }
        float4 ssum = make_float4(0.f, 0.f, 0.f, 0.f);
        #pragma unroll
        for (int b = 0; b < 8; b++) {
            a[b].x = fexp2(1.4426950408889634f * (a[b].x - mx.x));
            a[b].y = fexp2(1.4426950408889634f * (a[b].y - mx.y));
            a[b].z = fexp2(1.4426950408889634f * (a[b].z - mx.z));
            a[b].w = fexp2(1.4426950408889634f * (a[b].w - mx.w));
            ssum.x += a[b].x; ssum.y += a[b].y; ssum.z += a[b].z; ssum.w += a[b].w;
        }
        float4 inv = make_float4(frcp(ssum.x), frcp(ssum.y), frcp(ssum.z), frcp(ssum.w));
        float* aggb = g_agg + (size_t)dst * 6144;
        const uint2* xj = (const uint2*)(g_out1h + (size_t)src * 6144);
        #pragma unroll
        for (int b = 0; b < 8; b++) {
            int m = b * 12 + l;
            float4 sj = h4_to_f4(xj[m * 16 + h4]);
            float4 msg;
            msg.x = a[b].x * inv.x * sj.x;
            msg.y = a[b].y * inv.y * sj.y;
            msg.z = a[b].z * inv.z * sj.z;
            msg.w = a[b].w * inv.w * sj.w;
            asm volatile("red.global.add.v4.f32 [%0], {%1,%2,%3,%4};"
                         :: "l"(aggb + m * 64 + h4 * 4), "f"(msg.x), "f"(msg.y),
                            "f"(msg.z), "f"(msg.w) : "memory");
        }
    }
}

// ---------------------------------------------------------------------------
// GRU2: 4 seqs/thread (proven structure) with float2-packed weights.
// wT2[k*193 + p*64 + j], p=0:(wi_r,wi_z) p=1:(wi_n,wh_r) p=2:(wh_z,wh_n)
// ---------------------------------------------------------------------------
extern "C" __global__ void gru2_kernel(const float* __restrict__ Wih,
                                       const float* __restrict__ Whh,
                                       const float* __restrict__ bih,
                                       const float* __restrict__ bhh,
                                       float* __restrict__ h2_out)
{
    extern __shared__ float sm[];
    float2* wT2 = (float2*)sm;                 // 64*193 float2 = 98816 B
    float* h_sh = sm + 24704;                  // 1024
    float* x_sh = sm + 24704 + 1024;           // 1024

    const int tid = threadIdx.x;
    const int grp = tid >> 6;
    const int j   = tid & 63;

    // stage weights: coalesced global reads, scalar smem scatter
    for (int idx = tid; idx < 12288; idx += 256) {
        int g = idx >> 6, k = idx & 63;
        int m = g >> 6, jj = g & 63;
        float vi = Wih[idx];
        float vh = Whh[idx];
        float* base = (float*)(wT2 + (size_t)k * 193 + jj);
        // Wih gate m: m=0 -> p0.x, m=1 -> p0.y, m=2 -> p1.x
        if (m == 0)      base[0]           = vi;
        else if (m == 1) base[1]           = vi;
        else             base[128]         = vi;   // p1.x = offset 64 float2 = 128 floats
        // Whh gate m: m=0 -> p1.y, m=1 -> p2.x, m=2 -> p2.y
        if (m == 0)      base[129]         = vh;
        else if (m == 1) base[256]         = vh;
        else             base[257]         = vh;
    }

    float br = bih[j], bz = bih[64 + j], bn = bih[128 + j];
    float cr = bhh[j], cz = bhh[64 + j], cn = bhh[128 + j];

    float h[4] = {0.f, 0.f, 0.f, 0.f};
    const int s0 = blockIdx.x * 16 + grp * 4;
    const float* xg = g_agg + (size_t)s0 * 768 + j;

    for (int l = 0; l < LL; l++) {
        float4 xv;
        xv.x = fmaxf(xg[0 * 768 + l * 64], 0.0f);
        xv.y = fmaxf(xg[1 * 768 + l * 64], 0.0f);
        xv.z = fmaxf(xg[2 * 768 + l * 64], 0.0f);
        xv.w = fmaxf(xg[3 * 768 + l * 64], 0.0f);
        *(float4*)&x_sh[grp * 256 + j * 4] = xv;
        *(float4*)&h_sh[grp * 256 + j * 4] = make_float4(h[0], h[1], h[2], h[3]);
        __syncthreads();

        float gr[4], gz[4], gn[4];
        #pragma unroll
        for (int s = 0; s < 4; s++) { gr[s] = br + cr; gz[s] = bz + cz; gn[s] = bn; }
        float ghn[4] = {cn, cn, cn, cn};

        const float2* wp = wT2 + j;
        const float* hp = h_sh + grp * 256;
        const float* xp = x_sh + grp * 256;
        #pragma unroll 2
        for (int k = 0; k < 64; k++) {
            float2 wA = wp[k * 193];          // wi_r, wi_z
            float2 wB = wp[k * 193 + 64];     // wi_n, wh_r
            float2 wC = wp[k * 193 + 128];    // wh_z, wh_n
            float4 xk = *(const float4*)&xp[k * 4];
            float4 hk = *(const float4*)&hp[k * 4];
            gr[0] = fmaf(xk.x, wA.x, gr[0]); gz[0] = fmaf(xk.x, wA.y, gz[0]); gn[0] = fmaf(xk.x, wB.x, gn[0]);
            gr[0] = fmaf(hk.x, wB.y, gr[0]); gz[0] = fmaf(hk.x, wC.x, gz[0]); ghn[0] = fmaf(hk.x, wC.y, ghn[0]);
            gr[1] = fmaf(xk.y, wA.x, gr[1]); gz[1] = fmaf(xk.y, wA.y, gz[1]); gn[1] = fmaf(xk.y, wB.x, gn[1]);
            gr[1] = fmaf(hk.y, wB.y, gr[1]); gz[1] = fmaf(hk.y, wC.x, gz[1]); ghn[1] = fmaf(hk.y, wC.y, ghn[1]);
            gr[2] = fmaf(xk.z, wA.x, gr[2]); gz[2] = fmaf(xk.z, wA.y, gz[2]); gn[2] = fmaf(xk.z, wB.x, gn[2]);
            gr[2] = fmaf(hk.z, wB.y, gr[2]); gz[2] = fmaf(hk.z, wC.x, gz[2]); ghn[2] = fmaf(hk.z, wC.y, ghn[2]);
            gr[3] = fmaf(xk.w, wA.x, gr[3]); gz[3] = fmaf(xk.w, wA.y, gz[3]); gn[3] = fmaf(xk.w, wB.x, gn[3]);
            gr[3] = fmaf(hk.w, wB.y, gr[3]); gz[3] = fmaf(hk.w, wC.x, gz[3]); ghn[3] = fmaf(hk.w, wC.y, ghn[3]);
        }
        #pragma unroll
        for (int s = 0; s < 4; s++) {
            float r = fsig(gr[s]);
            float z = fsig(gz[s]);
            float n = ftanh(fmaf(r, ghn[s], gn[s]));
            h[s] = fmaf(z, h[s] - n, n);
        }
        __syncthreads();
    }
    #pragma unroll
    for (int s = 0; s < 4; s++)
        h2_out[(s0 + s) * 64 + j] = h[s];
}

// ---------------------------------------------------------------------------

static const int GRU1_SMEM = (12352 + 1024 + 384) * 4;
static const int GRU2_SMEM = (24704 + 1024 + 1024) * 4;   // 107,008 B

extern "C" void kernel_launch(void* const* d_in, const int* in_sizes, int n_in,
                              void* d_out, int out_size)
{
    const float* data     = (const float*)d_in[0];
    const float* features = (const float*)d_in[1];
    const int*   ei       = (const int*)  d_in[2];
    const float* Wih1     = (const float*)d_in[3];
    const float* Whh1     = (const float*)d_in[4];
    const float* bih1     = (const float*)d_in[5];
    const float* bhh1     = (const float*)d_in[6];
    const float* W1       = (const float*)d_in[7];
    const float* b1       = (const float*)d_in[8];
    const float* W2       = (const float*)d_in[9];
    const float* b2       = (const float*)d_in[10];
    const float* W3       = (const float*)d_in[11];
    const float* b3       = (const float*)d_in[12];
    const float* Wih2     = (const float*)d_in[13];
    const float* Whh2     = (const float*)d_in[14];
    const float* bih2     = (const float*)d_in[15];
    const float* bhh2     = (const float*)d_in[16];
    float* out = (float*)d_out;

    cudaFuncSetAttribute(gru1_kernel, cudaFuncAttributeMaxDynamicSharedMemorySize, GRU1_SMEM);
    cudaFuncSetAttribute(gru2_kernel, cudaFuncAttributeMaxDynamicSharedMemorySize, GRU2_SMEM);
    cudaFuncSetAttribute(precomp_kernel, cudaFuncAttributeMaxDynamicSharedMemorySize, PC_SMEM);

    // edge binning (independent of GRU outputs)
    bin_zero_kernel<<<8, 256>>>();
    bin_count_kernel<<<(EE + 255) / 256, 256>>>(ei);
    bin_scan_kernel<<<1, 1024>>>();
    bin_fill_kernel<<<(EE + 255) / 256, 256>>>(ei);

    gru1_kernel<<<NSEQ / 16, 256, GRU1_SMEM>>>(data, Wih1, Whh1, bih1, bhh1, out);
    precomp_kernel<<<PRE_GRID, 256, PC_SMEM>>>(W3, b3);
    zero_agg_kernel<<<2048, 256>>>();
    edge_stream_kernel<<<ETOT, 256, ES_SMEM>>>(features, W1, b1, W2, b2);
    gru2_kernel<<<NSEQ / 16, 256, GRU2_SMEM>>>(Wih2, Whh2, bih2, bhh2, out + NSEQ * HH);
}